// round 3
// baseline (speedup 1.0000x reference)
#include <cuda_runtime.h>
#include <cuda_bf16.h>
#include <math.h>

#define BATCH 32
#define NGT 20
#define HWA 10647
#define NUM_CLASSES 80
#define FP16_EPS_F 0.0009765625
#define BCE_EPS 1e-6f

#define TOTAL (BATCH * HWA)     // 340704
#define TOTAL4 (TOTAL / 4)      // 85176 exact
#define THREADS 256
#define MAIN_BLOCKS 116
#define GRID_BLOCKS (MAIN_BLOCKS + BATCH)  // 148 = one full wave

// persistent device state (no zero kernel needed):
// g_part_sum : plain-stored every call by main blocks
// g_batch    : plain-stored every call by correction blocks (7 doubles per batch)
//   [0]=cls  [1]=txty  [2]=twth  [3]=npos  [4]=conf_pos  [5]=negsub  [6]=touched
// g_done     : self-resetting last-block-done counter (0 at entry of every call)
__device__ double g_part_sum[MAIN_BLOCKS];
__device__ double g_batch[BATCH][7];
__device__ unsigned int g_done;  // zero-initialized; reset to 0 by final block

__constant__ float c_anc[9][2] = {
    {0.024f, 0.031f}, {0.038f, 0.072f}, {0.079f, 0.055f},
    {0.072f, 0.147f}, {0.142f, 0.286f}, {0.142f, 0.286f},
    {0.279f, 0.216f}, {0.375f, 0.476f}, {0.897f, 0.784f}};
// NOTE: row 4 corrected below via initializer — keep authoritative table here:
__constant__ float c_anc_fix[9][2] = {
    {0.024f, 0.031f}, {0.038f, 0.072f}, {0.079f, 0.055f},
    {0.072f, 0.147f}, {0.149f, 0.108f}, {0.142f, 0.286f},
    {0.279f, 0.216f}, {0.375f, 0.476f}, {0.897f, 0.784f}};

__device__ __forceinline__ int grid_of(int j) { return (j == 0) ? 52 : ((j == 1) ? 26 : 13); }
__device__ __forceinline__ int off_of(int j)  { return (j == 0) ? 0  : ((j == 1) ? 2704 : 3380); }

__device__ __forceinline__ float sigf(float x) { return 1.0f / (1.0f + expf(-x)); }
__device__ __forceinline__ float bcef(float p, float g) {
    p = fminf(fmaxf(p, BCE_EPS), 1.0f - BCE_EPS);
    return -(g * logf(p) + (1.0f - g) * logf(1.0f - p));
}

__device__ __forceinline__ double blk_reduce_d(double v, double* sh) {
    // 256 threads -> 8 warps
    #pragma unroll
    for (int s = 16; s > 0; s >>= 1) v += __shfl_xor_sync(0xFFFFFFFFu, v, s);
    int lane = threadIdx.x & 31, warp = threadIdx.x >> 5;
    if (lane == 0) sh[warp] = v;
    __syncthreads();
    double r = 0.0;
    if (threadIdx.x == 0) {
        #pragma unroll
        for (int w = 0; w < THREADS / 32; w++) r += sh[w];
    }
    __syncthreads();
    return r;
}

__global__ void __launch_bounds__(THREADS, 1)
yolo_loss_kernel(const float* __restrict__ pconf,
                 const float* __restrict__ pcls,
                 const float* __restrict__ ptxywh,
                 const float* __restrict__ gb,
                 const int* __restrict__ glab,
                 float* __restrict__ out) {
    __shared__ double sh_red[THREADS / 32];

    int blk = blockIdx.x;

    if (blk < MAIN_BLOCKS) {
        // ---- main: sum sigmoid(pconf)^2 over all rows (as-if-all-negative) ----
        const float4* pc4 = (const float4*)pconf;
        float acc = 0.0f;
        for (int idx = blk * THREADS + threadIdx.x; idx < TOTAL4;
             idx += MAIN_BLOCKS * THREADS) {
            float4 v = pc4[idx];
            float s0 = sigf(v.x), s1 = sigf(v.y), s2 = sigf(v.z), s3 = sigf(v.w);
            acc += s0 * s0 + s1 * s1 + s2 * s2 + s3 * s3;
        }
        double tot = blk_reduce_d((double)acc, sh_red);
        if (threadIdx.x == 0) g_part_sum[blk] = tot;
    } else {
        // ---- correction: one block per batch item ----
        int b = blk - MAIN_BLOCKS;
        __shared__ float scx[NGT], scy[NGT], sw[NGT], shh[NGT];
        __shared__ int sa[NGT];
        __shared__ int scell[NGT][3];   // base row index (already *3) per (i,j)

        int tid = threadIdx.x;
        if (tid < NGT) {
            const float* p = gb + (b * NGT + tid) * 4;
            float l = p[0], tp = p[1], r = p[2], bo = p[3];
            float cx = (l + r) * 0.5f, cy = (tp + bo) * 0.5f;
            float w = r - l, h = bo - tp;
            scx[tid] = cx; scy[tid] = cy; sw[tid] = w; shh[tid] = h;
            float area = w * h;
            float best = -1.0f; int bi = 0;
            #pragma unroll
            for (int a = 0; a < 9; a++) {
                float aw = c_anc_fix[a][0], ah = c_anc_fix[a][1];
                float inter = fminf(w, aw) * fminf(h, ah);
                float uni = area + aw * ah - inter;
                float iou = inter / uni;
                if (iou > best) { best = iou; bi = a; }  // first-max like argmax
            }
            sa[tid] = bi;
            #pragma unroll
            for (int j = 0; j < 3; j++) {
                int grid = grid_of(j), off = off_of(j);
                int col = (int)(cx * (float)grid);
                int row = (int)(cy * (float)grid);
                scell[tid][j] = (off + row * grid + col) * 3;
            }
        }
        __syncthreads();

        double cls_s = 0.0, txty_s = 0.0, twth_s = 0.0, cpos_s = 0.0, negsub_s = 0.0;
        int npos_i = 0, touched_i = 0;

        if (tid < NGT * 9) {
            int i = tid / 9;
            int j = (tid % 9) / 3;
            int s = tid % 3;
            int C = scell[i][j];

            // owner dedupe: min-i per (cell, j)
            bool owner = true;
            for (int i2 = 0; i2 < i; i2++)
                if (scell[i2][j] == C) { owner = false; break; }

            if (owner) {
                // replay priority contest: winner = max packed event
                // pr(neg,i',k=19,j) = 2*(3*(i'*20+19)+j)    (even)
                // pr(pos,i',k)      = 2*(3*(i'*20+k)+j)+1   (odd), payload (i',a)
                unsigned int win = 0u;
                for (int i2 = 0; i2 < NGT; i2++) {
                    if (scell[i2][j] != C) continue;
                    unsigned int prn = 2u * (unsigned int)(3 * (i2 * NGT + NGT - 1) + j);
                    unsigned int vn = prn << 9;
                    if (vn > win) win = vn;
                    #pragma unroll 4
                    for (int k = 0; k < NGT; k++) {
                        int a = sa[k];
                        if ((a / 3) == j && (a % 3) == s) {
                            unsigned int prp = 2u * (unsigned int)(3 * (i2 * NGT + k) + j) + 1u;
                            unsigned int vp = (prp << 9) | ((unsigned int)i2 << 4) | (unsigned int)a;
                            if (vp > win) win = vp;
                        }
                    }
                }
                // every candidate row receives at least its own neg event
                int row = C + s;
                int t = b * HWA + row;
                float sc = sigf(pconf[t]);
                negsub_s = (double)(sc * sc);
                touched_i = 1;

                if ((win >> 9) & 1u) {
                    // positive row
                    int iw = (int)((win >> 4) & 0x1Fu);
                    int a  = (int)(win & 0xFu);
                    float d = sc - 1.0f;
                    cpos_s = (double)(d * d);
                    npos_i = 1;

                    float cx = scx[iw], cy = scy[iw], w = sw[iw], h = shh[iw];
                    int jj = a / 3;
                    float gridf = (float)grid_of(jj);
                    int col = (int)(cx * gridf);
                    int rowg = (int)(cy * gridf);
                    float tx = (cx - (float)col / gridf) * gridf;
                    float ty = (cy - (float)rowg / gridf) * gridf;
                    float twx = logf(w / c_anc_fix[a][0]);
                    float twy = logf(h / c_anc_fix[a][1]);
                    float wt = 2.0f - w * h;
                    int lbl = glab[b * NGT + iw] - 1;

                    const float* pcp = pcls + (size_t)t * NUM_CLASSES;
                    float cls = 0.0f;
                    #pragma unroll 8
                    for (int c = 0; c < NUM_CLASSES; c++) {
                        float p = sigf(pcp[c]);
                        p = fminf(fmaxf(p, BCE_EPS), 1.0f - BCE_EPS);
                        cls += (c == lbl) ? -logf(p) : -logf(1.0f - p);
                    }
                    cls_s = (double)cls;

                    const float* pt = ptxywh + (size_t)t * 4;
                    float bce_xy = bcef(sigf(pt[0]), tx) + bcef(sigf(pt[1]), ty);
                    txty_s = (double)(bce_xy * wt);
                    float d2 = pt[2] - twx, d3 = pt[3] - twy;
                    twth_s = (double)((d2 * d2 + d3 * d3) * wt);
                }
            }
        }

        double r;
        r = blk_reduce_d(cls_s, sh_red);    if (tid == 0) g_batch[b][0] = r;
        r = blk_reduce_d(txty_s, sh_red);   if (tid == 0) g_batch[b][1] = r;
        r = blk_reduce_d(twth_s, sh_red);   if (tid == 0) g_batch[b][2] = r;
        r = blk_reduce_d((double)npos_i, sh_red);    if (tid == 0) g_batch[b][3] = r;
        r = blk_reduce_d(cpos_s, sh_red);   if (tid == 0) g_batch[b][4] = r;
        r = blk_reduce_d(negsub_s, sh_red); if (tid == 0) g_batch[b][5] = r;
        r = blk_reduce_d((double)touched_i, sh_red); if (tid == 0) g_batch[b][6] = r;
    }

    // ---- last-block-done: final combine ----
    __shared__ unsigned int s_is_last;
    __threadfence();
    __syncthreads();
    if (threadIdx.x == 0) {
        unsigned int prev = atomicAdd(&g_done, 1u);
        s_is_last = (prev == (unsigned int)(gridDim.x - 1)) ? 1u : 0u;
    }
    __syncthreads();
    if (!s_is_last) return;

    __threadfence();

    // sum main partials (256 threads, strided)
    double part = 0.0;
    for (int i = threadIdx.x; i < MAIN_BLOCKS; i += THREADS) part += g_part_sum[i];
    double all_sum = blk_reduce_d(part, sh_red);
    __shared__ double sh_all;
    if (threadIdx.x == 0) sh_all = all_sum;

    // per-batch combine on first warp
    double pb = 0.0, npos = 0.0, cpos = 0.0, negsub = 0.0, touched = 0.0;
    if (threadIdx.x < BATCH) {
        int b = threadIdx.x;
        double np = g_batch[b][3];
        double npc = (np < (double)FP16_EPS_F) ? (double)FP16_EPS_F : np;
        pb = (g_batch[b][0] + g_batch[b][1] + g_batch[b][2]) / npc;
        npos = np;
        cpos = g_batch[b][4];
        negsub = g_batch[b][5];
        touched = g_batch[b][6];
    }
    if (threadIdx.x < 32) {
        #pragma unroll
        for (int s = 16; s > 0; s >>= 1) {
            pb      += __shfl_xor_sync(0xFFFFFFFFu, pb, s);
            npos    += __shfl_xor_sync(0xFFFFFFFFu, npos, s);
            cpos    += __shfl_xor_sync(0xFFFFFFFFu, cpos, s);
            negsub  += __shfl_xor_sync(0xFFFFFFFFu, negsub, s);
            touched += __shfl_xor_sync(0xFFFFFFFFu, touched, s);
        }
    }
    __syncthreads();
    if (threadIdx.x == 0) {
        double conf_neg_sum = sh_all - negsub;
        double neg_count = (double)TOTAL - touched;
        double l_conf_pos = cpos / npos * 30.0;
        double l_conf_neg = conf_neg_sum / neg_count * 30.0;
        out[0] = (float)(l_conf_pos + l_conf_neg + pb / (double)BATCH);
        g_done = 0u;  // self-reset: identical state at entry of every call
    }
}

extern "C" void kernel_launch(void* const* d_in, const int* in_sizes, int n_in,
                              void* d_out, int out_size) {
    const float* pconf  = (const float*)d_in[0];
    const float* pcls   = (const float*)d_in[1];
    const float* ptxywh = (const float*)d_in[2];
    const float* gb     = (const float*)d_in[3];
    const int*   glab   = (const int*)d_in[4];
    float* out = (float*)d_out;

    yolo_loss_kernel<<<GRID_BLOCKS, THREADS>>>(pconf, pcls, ptxywh, gb, glab, out);
}

// round 4
// speedup vs baseline: 2.1793x; 2.1793x over previous
#include <cuda_runtime.h>
#include <cuda_bf16.h>
#include <math.h>

#define BATCH 32
#define NGT 20
#define HWA 10647
#define NUM_CLASSES 80
#define FP16_EPS_F 0.0009765625
#define BCE_EPS 1e-6f

#define TOTAL (BATCH * HWA)     // 340704
#define TOTAL4 (TOTAL / 4)      // 85176 exact
#define THREADS 256
#define MAIN_BLOCKS 296
#define GRID_BLOCKS (MAIN_BLOCKS + BATCH)  // 328

// persistent device state (plain-stored every call; no zeroing needed)
// g_batch[b]: [0]=cls [1]=txty [2]=twth [3]=npos [4]=conf_pos [5]=negsub [6]=touched
__device__ double g_part_sum[MAIN_BLOCKS];
__device__ double g_batch[BATCH][7];
__device__ unsigned int g_done;  // zero-init; self-reset by final block

__constant__ float c_anc[9][2] = {
    {0.024f, 0.031f}, {0.038f, 0.072f}, {0.079f, 0.055f},
    {0.072f, 0.147f}, {0.149f, 0.108f}, {0.142f, 0.286f},
    {0.279f, 0.216f}, {0.375f, 0.476f}, {0.897f, 0.784f}};

__device__ __forceinline__ int grid_of(int j) { return (j == 0) ? 52 : ((j == 1) ? 26 : 13); }
__device__ __forceinline__ int off_of(int j)  { return (j == 0) ? 0  : ((j == 1) ? 2704 : 3380); }

// fast sigmoid: 2 MUFU (EX2 + RCP-approx). Used identically for ALL pconf reads
// so the touched-row subtraction cancels bitwise against the main sum.
__device__ __forceinline__ float sigf(float x) {
    return __fdividef(1.0f, 1.0f + __expf(-x));
}
__device__ __forceinline__ float bcef(float p, float g) {
    p = fminf(fmaxf(p, BCE_EPS), 1.0f - BCE_EPS);
    return -(g * logf(p) + (1.0f - g) * logf(1.0f - p));
}

__device__ __forceinline__ double blk_reduce_d(double v, double* sh) {
    #pragma unroll
    for (int s = 16; s > 0; s >>= 1) v += __shfl_xor_sync(0xFFFFFFFFu, v, s);
    int lane = threadIdx.x & 31, warp = threadIdx.x >> 5;
    if (lane == 0) sh[warp] = v;
    __syncthreads();
    double r = 0.0;
    if (threadIdx.x == 0) {
        #pragma unroll
        for (int w = 0; w < THREADS / 32; w++) r += sh[w];
    }
    __syncthreads();
    return r;
}

__global__ void __launch_bounds__(THREADS)
yolo_loss_kernel(const float* __restrict__ pconf,
                 const float* __restrict__ pcls,
                 const float* __restrict__ ptxywh,
                 const float* __restrict__ gb,
                 const int* __restrict__ glab,
                 float* __restrict__ out) {
    __shared__ double sh_red[THREADS / 32];
    int blk = blockIdx.x;

    if (blk < MAIN_BLOCKS) {
        // ---- main: sum sigmoid(pconf)^2 over all rows (as-if-all-negative) ----
        const float4* pc4 = (const float4*)pconf;
        float acc = 0.0f;
        #pragma unroll 2
        for (int idx = blk * THREADS + threadIdx.x; idx < TOTAL4;
             idx += MAIN_BLOCKS * THREADS) {
            float4 v = pc4[idx];
            float s0 = sigf(v.x), s1 = sigf(v.y), s2 = sigf(v.z), s3 = sigf(v.w);
            acc += s0 * s0 + s1 * s1 + s2 * s2 + s3 * s3;
        }
        double tot = blk_reduce_d((double)acc, sh_red);
        if (threadIdx.x == 0) g_part_sum[blk] = tot;
    } else {
        // ---- correction: one block per batch item (closed-form winners) ----
        int b = blk - MAIN_BLOCKS;
        __shared__ float scx[NGT], scy[NGT], swd[NGT], shd[NGT];
        __shared__ int scell[NGT][3];
        __shared__ int s_a19;

        int tid = threadIdx.x;
        if (tid < NGT) {
            const float* p = gb + (b * NGT + tid) * 4;
            float l = p[0], tp = p[1], r = p[2], bo = p[3];
            float cx = (l + r) * 0.5f, cy = (tp + bo) * 0.5f;
            float w = r - l, h = bo - tp;
            scx[tid] = cx; scy[tid] = cy; swd[tid] = w; shd[tid] = h;
            #pragma unroll
            for (int j = 0; j < 3; j++) {
                int grid = grid_of(j), off = off_of(j);
                int col = (int)(cx * (float)grid);
                int row = (int)(cy * (float)grid);
                scell[tid][j] = (off + row * grid + col) * 3;
            }
            if (tid == NGT - 1) {
                // anchor argmax for GT #19 only (the only k whose pos events survive)
                float area = w * h;
                float best = -1.0f; int bi = 0;
                #pragma unroll
                for (int a = 0; a < 9; a++) {
                    float aw = c_anc[a][0], ah = c_anc[a][1];
                    float inter = fminf(w, aw) * fminf(h, ah);
                    float uni = area + aw * ah - inter;
                    float iou = inter / uni;
                    if (iou > best) { best = iou; bi = a; }  // first-max like argmax
                }
                s_a19 = bi;
            }
        }
        __syncthreads();

        double cls_s = 0.0, txty_s = 0.0, twth_s = 0.0, cpos_s = 0.0, negsub_s = 0.0;
        double npos_d = 0.0, touched_d = 0.0;

        if (tid < NGT * 3) {
            int i = tid / 3;
            int j = tid % 3;
            int C = scell[i][j];
            // owner = i2max of this (cell, scale)
            bool owner = true;
            for (int i2 = i + 1; i2 < NGT; i2++)
                if (scell[i2][j] == C) { owner = false; break; }

            if (owner) {
                int t0 = b * HWA + C;
                float sc0 = sigf(pconf[t0]);
                float sc1 = sigf(pconf[t0 + 1]);
                float sc2 = sigf(pconf[t0 + 2]);
                negsub_s = (double)(sc0 * sc0 + sc1 * sc1 + sc2 * sc2);
                touched_d = 3.0;

                int a19 = s_a19;
                int js = a19 / 3, ss = a19 % 3;
                if (j == js) {
                    // positive row: slot ss, payload i (== i2max), anchor a19
                    int t = t0 + ss;
                    float sc = (ss == 0) ? sc0 : ((ss == 1) ? sc1 : sc2);
                    float d = sc - 1.0f;
                    cpos_s = (double)(d * d);
                    npos_d = 1.0;

                    float cx = scx[i], cy = scy[i], w = swd[i], h = shd[i];
                    float gridf = (float)grid_of(j);
                    int col = (int)(cx * gridf);
                    int rowg = (int)(cy * gridf);
                    float tx = (cx - (float)col / gridf) * gridf;
                    float ty = (cy - (float)rowg / gridf) * gridf;
                    float twx = logf(w / c_anc[a19][0]);
                    float twy = logf(h / c_anc[a19][1]);
                    float wt = 2.0f - w * h;
                    int lbl = glab[b * NGT + i] - 1;

                    const float* pcp = pcls + (size_t)t * NUM_CLASSES;
                    float cls = 0.0f;
                    #pragma unroll 8
                    for (int c = 0; c < NUM_CLASSES; c++) {
                        float p = 1.0f / (1.0f + expf(-pcp[c]));
                        p = fminf(fmaxf(p, BCE_EPS), 1.0f - BCE_EPS);
                        cls += (c == lbl) ? -logf(p) : -logf(1.0f - p);
                    }
                    cls_s = (double)cls;

                    const float* pt = ptxywh + (size_t)t * 4;
                    float p0 = 1.0f / (1.0f + expf(-pt[0]));
                    float p1 = 1.0f / (1.0f + expf(-pt[1]));
                    float bce_xy = bcef(p0, tx) + bcef(p1, ty);
                    txty_s = (double)(bce_xy * wt);
                    float d2 = pt[2] - twx, d3 = pt[3] - twy;
                    twth_s = (double)((d2 * d2 + d3 * d3) * wt);
                }
            }
        }

        double r;
        r = blk_reduce_d(cls_s, sh_red);    if (tid == 0) g_batch[b][0] = r;
        r = blk_reduce_d(txty_s, sh_red);   if (tid == 0) g_batch[b][1] = r;
        r = blk_reduce_d(twth_s, sh_red);   if (tid == 0) g_batch[b][2] = r;
        r = blk_reduce_d(npos_d, sh_red);   if (tid == 0) g_batch[b][3] = r;
        r = blk_reduce_d(cpos_s, sh_red);   if (tid == 0) g_batch[b][4] = r;
        r = blk_reduce_d(negsub_s, sh_red); if (tid == 0) g_batch[b][5] = r;
        r = blk_reduce_d(touched_d, sh_red);if (tid == 0) g_batch[b][6] = r;
    }

    // ---- last-block-done: final combine (fence from thread 0 only) ----
    __shared__ unsigned int s_is_last;
    if (threadIdx.x == 0) {
        __threadfence();
        unsigned int prev = atomicAdd(&g_done, 1u);
        s_is_last = (prev == (unsigned int)(gridDim.x - 1)) ? 1u : 0u;
    }
    __syncthreads();
    if (!s_is_last) return;
    if (threadIdx.x == 0) __threadfence();
    __syncthreads();

    // sum main partials
    double part = 0.0;
    for (int i = threadIdx.x; i < MAIN_BLOCKS; i += THREADS) part += g_part_sum[i];
    double all_sum = blk_reduce_d(part, sh_red);
    __shared__ double sh_all;
    if (threadIdx.x == 0) sh_all = all_sum;

    double pb = 0.0, npos = 0.0, cpos = 0.0, negsub = 0.0, touched = 0.0;
    if (threadIdx.x < BATCH) {
        int b = threadIdx.x;
        double np = g_batch[b][3];
        double npc = (np < (double)FP16_EPS_F) ? (double)FP16_EPS_F : np;
        pb = (g_batch[b][0] + g_batch[b][1] + g_batch[b][2]) / npc;
        npos = np;
        cpos = g_batch[b][4];
        negsub = g_batch[b][5];
        touched = g_batch[b][6];
    }
    if (threadIdx.x < 32) {
        #pragma unroll
        for (int s = 16; s > 0; s >>= 1) {
            pb      += __shfl_xor_sync(0xFFFFFFFFu, pb, s);
            npos    += __shfl_xor_sync(0xFFFFFFFFu, npos, s);
            cpos    += __shfl_xor_sync(0xFFFFFFFFu, cpos, s);
            negsub  += __shfl_xor_sync(0xFFFFFFFFu, negsub, s);
            touched += __shfl_xor_sync(0xFFFFFFFFu, touched, s);
        }
    }
    __syncthreads();
    if (threadIdx.x == 0) {
        double conf_neg_sum = sh_all - negsub;
        double neg_count = (double)TOTAL - touched;
        double l_conf_pos = cpos / npos * 30.0;
        double l_conf_neg = conf_neg_sum / neg_count * 30.0;
        out[0] = (float)(l_conf_pos + l_conf_neg + pb / (double)BATCH);
        g_done = 0u;  // self-reset for next graph replay
    }
}

extern "C" void kernel_launch(void* const* d_in, const int* in_sizes, int n_in,
                              void* d_out, int out_size) {
    const float* pconf  = (const float*)d_in[0];
    const float* pcls   = (const float*)d_in[1];
    const float* ptxywh = (const float*)d_in[2];
    const float* gb     = (const float*)d_in[3];
    const int*   glab   = (const int*)d_in[4];
    float* out = (float*)d_out;

    yolo_loss_kernel<<<GRID_BLOCKS, THREADS>>>(pconf, pcls, ptxywh, gb, glab, out);
}

// round 5
// speedup vs baseline: 3.0417x; 1.3957x over previous
#include <cuda_runtime.h>
#include <cuda_bf16.h>
#include <math.h>

#define BATCH 32
#define NGT 20
#define HWA 10647
#define NUM_CLASSES 80
#define FP16_EPS_F 0.0009765625
#define BCE_EPS 1e-6f

#define TOTAL (BATCH * HWA)     // 340704
#define TOTAL4 (TOTAL / 4)      // 85176 exact
#define THREADS 256
#define MAIN_BLOCKS 333         // 333*256 = 85248 >= TOTAL4, 1 float4/thread
#define GRID_BLOCKS (MAIN_BLOCKS + BATCH)  // 365

// persistent device state (plain-stored every call; no zeroing needed)
// g_batch[b]: [0]=cls [1]=txty [2]=twth [3]=npos [4]=conf_pos [5]=negsub [6]=touched
__device__ float g_part_sum[MAIN_BLOCKS];
__device__ float g_batch[BATCH][7];
__device__ unsigned int g_done;  // zero-init; self-reset by final block

__constant__ float c_anc[9][2] = {
    {0.024f, 0.031f}, {0.038f, 0.072f}, {0.079f, 0.055f},
    {0.072f, 0.147f}, {0.149f, 0.108f}, {0.142f, 0.286f},
    {0.279f, 0.216f}, {0.375f, 0.476f}, {0.897f, 0.784f}};

__device__ __forceinline__ int grid_of(int j) { return (j == 0) ? 52 : ((j == 1) ? 26 : 13); }
__device__ __forceinline__ int off_of(int j)  { return (j == 0) ? 0  : ((j == 1) ? 2704 : 3380); }

// fast sigmoid: EX2 + RCP. Used identically for main sum and touched-row
// subtraction so the correction cancels to ~1ulp.
__device__ __forceinline__ float sigf(float x) {
    return __fdividef(1.0f, 1.0f + __expf(-x));
}
__device__ __forceinline__ float bcef(float p, float g) {
    p = fminf(fmaxf(p, BCE_EPS), 1.0f - BCE_EPS);
    return -(g * logf(p) + (1.0f - g) * logf(1.0f - p));
}

__device__ __forceinline__ float warp_sum_f(float v) {
    #pragma unroll
    for (int s = 16; s > 0; s >>= 1) v += __shfl_xor_sync(0xFFFFFFFFu, v, s);
    return v;
}

__global__ void __launch_bounds__(THREADS)
yolo_loss_kernel(const float* __restrict__ pconf,
                 const float* __restrict__ pcls,
                 const float* __restrict__ ptxywh,
                 const float* __restrict__ gb,
                 const int* __restrict__ glab,
                 float* __restrict__ out) {
    __shared__ float sh_red[THREADS / 32];
    int blk = blockIdx.x;
    int tid = threadIdx.x;
    int lane = tid & 31, warp = tid >> 5;

    if (blk < MAIN_BLOCKS) {
        // ---- main: sum sigmoid(pconf)^2 over all rows, 1 float4/thread ----
        int idx = blk * THREADS + tid;
        float acc = 0.0f;
        if (idx < TOTAL4) {
            float4 v = ((const float4*)pconf)[idx];
            float s0 = sigf(v.x), s1 = sigf(v.y), s2 = sigf(v.z), s3 = sigf(v.w);
            acc = s0 * s0 + s1 * s1 + s2 * s2 + s3 * s3;
        }
        acc = warp_sum_f(acc);
        if (lane == 0) sh_red[warp] = acc;
        __syncthreads();
        if (tid == 0) {
            float t = 0.0f;
            #pragma unroll
            for (int w = 0; w < THREADS / 32; w++) t += sh_red[w];
            g_part_sum[blk] = t;
        }
    } else {
        // ---- correction: one block per batch item (closed-form winners) ----
        int b = blk - MAIN_BLOCKS;
        __shared__ float scx[NGT], scy[NGT], swd[NGT], shd[NGT];
        __shared__ int scell[NGT][3];
        __shared__ int s_a19;
        __shared__ float s_out[2][7];

        if (tid < NGT) {
            const float* p = gb + (b * NGT + tid) * 4;
            float l = p[0], tp = p[1], r = p[2], bo = p[3];
            float cx = (l + r) * 0.5f, cy = (tp + bo) * 0.5f;
            float w = r - l, h = bo - tp;
            scx[tid] = cx; scy[tid] = cy; swd[tid] = w; shd[tid] = h;
            #pragma unroll
            for (int j = 0; j < 3; j++) {
                int grid = grid_of(j), off = off_of(j);
                int col = (int)(cx * (float)grid);
                int row = (int)(cy * (float)grid);
                scell[tid][j] = (off + row * grid + col) * 3;
            }
            if (tid == NGT - 1) {
                // anchor argmax for GT #19 (only k whose positive events survive)
                float area = w * h;
                float best = -1.0f; int bi = 0;
                #pragma unroll
                for (int a = 0; a < 9; a++) {
                    float aw = c_anc[a][0], ah = c_anc[a][1];
                    float inter = fminf(w, aw) * fminf(h, ah);
                    float uni = area + aw * ah - inter;
                    float iou = inter / uni;
                    if (iou > best) { best = iou; bi = a; }  // first-max like argmax
                }
                s_a19 = bi;
            }
        }
        __syncthreads();

        float v0 = 0.f, v1 = 0.f, v2 = 0.f, v3 = 0.f, v4 = 0.f, v5 = 0.f, v6 = 0.f;
        // v: cls, txty, twth, npos, conf_pos, negsub, touched

        if (tid < NGT * 3) {
            int i = tid / 3;
            int j = tid % 3;
            int C = scell[i][j];
            // owner = max-i sharing this (cell, scale)
            bool owner = true;
            for (int i2 = i + 1; i2 < NGT; i2++)
                if (scell[i2][j] == C) { owner = false; break; }

            if (owner) {
                int t0 = b * HWA + C;
                float sc0 = sigf(pconf[t0]);
                float sc1 = sigf(pconf[t0 + 1]);
                float sc2 = sigf(pconf[t0 + 2]);
                v5 = sc0 * sc0 + sc1 * sc1 + sc2 * sc2;
                v6 = 3.0f;

                int a19 = s_a19;
                int js = a19 / 3, ss = a19 % 3;
                if (j == js) {
                    int t = t0 + ss;
                    float sc = (ss == 0) ? sc0 : ((ss == 1) ? sc1 : sc2);
                    float d = sc - 1.0f;
                    v4 = d * d;
                    v3 = 1.0f;

                    float cx = scx[i], cy = scy[i], w = swd[i], h = shd[i];
                    float gridf = (float)grid_of(j);
                    int col = (int)(cx * gridf);
                    int rowg = (int)(cy * gridf);
                    float tx = (cx - (float)col / gridf) * gridf;
                    float ty = (cy - (float)rowg / gridf) * gridf;
                    float twx = logf(w / c_anc[a19][0]);
                    float twy = logf(h / c_anc[a19][1]);
                    float wt = 2.0f - w * h;
                    int lbl = glab[b * NGT + i] - 1;

                    const float* pcp = pcls + (size_t)t * NUM_CLASSES;
                    float cls = 0.0f;
                    #pragma unroll 8
                    for (int c = 0; c < NUM_CLASSES; c++) {
                        float p = 1.0f / (1.0f + expf(-pcp[c]));
                        p = fminf(fmaxf(p, BCE_EPS), 1.0f - BCE_EPS);
                        cls += (c == lbl) ? -logf(p) : -logf(1.0f - p);
                    }
                    v0 = cls;

                    const float* pt = ptxywh + (size_t)t * 4;
                    float p0 = 1.0f / (1.0f + expf(-pt[0]));
                    float p1 = 1.0f / (1.0f + expf(-pt[1]));
                    v1 = (bcef(p0, tx) + bcef(p1, ty)) * wt;
                    float d2 = pt[2] - twx, d3 = pt[3] - twy;
                    v2 = (d2 * d2 + d3 * d3) * wt;
                }
            }
        }

        // single-pass reduce: only warps 0,1 carry data (tid < 60)
        if (warp < 2) {
            v0 = warp_sum_f(v0); v1 = warp_sum_f(v1); v2 = warp_sum_f(v2);
            v3 = warp_sum_f(v3); v4 = warp_sum_f(v4); v5 = warp_sum_f(v5);
            v6 = warp_sum_f(v6);
            if (lane == 0) {
                s_out[warp][0] = v0; s_out[warp][1] = v1; s_out[warp][2] = v2;
                s_out[warp][3] = v3; s_out[warp][4] = v4; s_out[warp][5] = v5;
                s_out[warp][6] = v6;
            }
        }
        __syncthreads();
        if (tid < 7) {
            g_batch[b][tid] = s_out[0][tid] + s_out[1][tid];
        }
    }

    // ---- last-block-done: final combine ----
    __shared__ unsigned int s_is_last;
    if (tid == 0) {
        __threadfence();
        unsigned int prev = atomicAdd(&g_done, 1u);
        s_is_last = (prev == (unsigned int)(GRID_BLOCKS - 1)) ? 1u : 0u;
    }
    __syncthreads();
    if (!s_is_last) return;
    if (tid == 0) __threadfence();
    __syncthreads();

    // sum main partials (333 floats)
    float part = 0.0f;
    for (int i = tid; i < MAIN_BLOCKS; i += THREADS) part += g_part_sum[i];
    part = warp_sum_f(part);
    if (lane == 0) sh_red[warp] = part;
    __syncthreads();
    __shared__ float sh_all;
    if (tid == 0) {
        float t = 0.0f;
        #pragma unroll
        for (int w = 0; w < THREADS / 32; w++) t += sh_red[w];
        sh_all = t;
    }

    float pb = 0.0f, npos = 0.0f, cpos = 0.0f, negsub = 0.0f, touched = 0.0f;
    if (tid < BATCH) {
        int b = tid;
        float np = g_batch[b][3];
        float npc = (np < FP16_EPS_F) ? FP16_EPS_F : np;
        pb = (g_batch[b][0] + g_batch[b][1] + g_batch[b][2]) / npc;
        npos = np;
        cpos = g_batch[b][4];
        negsub = g_batch[b][5];
        touched = g_batch[b][6];
    }
    if (tid < 32) {
        pb = warp_sum_f(pb);
        npos = warp_sum_f(npos);
        cpos = warp_sum_f(cpos);
        negsub = warp_sum_f(negsub);
        touched = warp_sum_f(touched);
    }
    __syncthreads();
    if (tid == 0) {
        double conf_neg_sum = (double)sh_all - (double)negsub;
        double neg_count = (double)TOTAL - (double)touched;
        double l_conf_pos = (double)cpos / (double)npos * 30.0;
        double l_conf_neg = conf_neg_sum / neg_count * 30.0;
        out[0] = (float)(l_conf_pos + l_conf_neg + (double)pb / (double)BATCH);
        g_done = 0u;  // self-reset for next graph replay
    }
}

extern "C" void kernel_launch(void* const* d_in, const int* in_sizes, int n_in,
                              void* d_out, int out_size) {
    const float* pconf  = (const float*)d_in[0];
    const float* pcls   = (const float*)d_in[1];
    const float* ptxywh = (const float*)d_in[2];
    const float* gb     = (const float*)d_in[3];
    const int*   glab   = (const int*)d_in[4];
    float* out = (float*)d_out;

    yolo_loss_kernel<<<GRID_BLOCKS, THREADS>>>(pconf, pcls, ptxywh, gb, glab, out);
}

// round 6
// speedup vs baseline: 4.0100x; 1.3183x over previous
#include <cuda_runtime.h>
#include <cuda_bf16.h>
#include <math.h>

#define BATCH 32
#define NGT 20
#define HWA 10647
#define NUM_CLASSES 80
#define FP16_EPS_F 0.0009765625
#define BCE_EPS 1e-6f

#define TOTAL (BATCH * HWA)     // 340704
#define TOTAL4 (TOTAL / 4)      // 85176 exact
#define THREADS 256
#define MAIN_BLOCKS 333         // 333*256 = 85248 >= TOTAL4, 1 float4/thread
#define GRID_BLOCKS (MAIN_BLOCKS + BATCH)  // 365

// persistent device state (plain-stored every call; no zeroing needed)
// g_batch[b]: [0]=cls [1]=txty [2]=twth [3]=npos [4]=conf_pos [5]=negsub [6]=touched
__device__ float g_part_sum[MAIN_BLOCKS];
__device__ float g_batch[BATCH][7];
__device__ unsigned int g_done;  // zero-init; self-reset by final block

__constant__ float c_anc[9][2] = {
    {0.024f, 0.031f}, {0.038f, 0.072f}, {0.079f, 0.055f},
    {0.072f, 0.147f}, {0.149f, 0.108f}, {0.142f, 0.286f},
    {0.279f, 0.216f}, {0.375f, 0.476f}, {0.897f, 0.784f}};

__device__ __forceinline__ int grid_of(int j) { return (j == 0) ? 52 : ((j == 1) ? 26 : 13); }
__device__ __forceinline__ int off_of(int j)  { return (j == 0) ? 0  : ((j == 1) ? 2704 : 3380); }

// fast sigmoid: EX2 + RCP. Used identically for main sum and touched-row
// subtraction so the correction cancels to ~1ulp.
__device__ __forceinline__ float sigf(float x) {
    return __fdividef(1.0f, 1.0f + __expf(-x));
}
__device__ __forceinline__ float bcef(float p, float g) {
    p = fminf(fmaxf(p, BCE_EPS), 1.0f - BCE_EPS);
    return -(g * __logf(p) + (1.0f - g) * __logf(1.0f - p));
}

__device__ __forceinline__ float warp_sum_f(float v) {
    #pragma unroll
    for (int s = 16; s > 0; s >>= 1) v += __shfl_xor_sync(0xFFFFFFFFu, v, s);
    return v;
}

__global__ void __launch_bounds__(THREADS)
yolo_loss_kernel(const float* __restrict__ pconf,
                 const float* __restrict__ pcls,
                 const float* __restrict__ ptxywh,
                 const float* __restrict__ gb,
                 const int* __restrict__ glab,
                 float* __restrict__ out) {
    __shared__ float sh_red[THREADS / 32];
    int blk = blockIdx.x;
    int tid = threadIdx.x;
    int lane = tid & 31, warp = tid >> 5;

    if (blk < MAIN_BLOCKS) {
        // ---- main: sum sigmoid(pconf)^2 over all rows, 1 float4/thread ----
        int idx = blk * THREADS + tid;
        float acc = 0.0f;
        if (idx < TOTAL4) {
            float4 v = ((const float4*)pconf)[idx];
            float s0 = sigf(v.x), s1 = sigf(v.y), s2 = sigf(v.z), s3 = sigf(v.w);
            acc = s0 * s0 + s1 * s1 + s2 * s2 + s3 * s3;
        }
        acc = warp_sum_f(acc);
        if (lane == 0) sh_red[warp] = acc;
        __syncthreads();
        if (tid == 0) {
            float t = 0.0f;
            #pragma unroll
            for (int w = 0; w < THREADS / 32; w++) t += sh_red[w];
            g_part_sum[blk] = t;
        }
    } else {
        // ---- correction: one block per batch item (closed-form winners) ----
        int b = blk - MAIN_BLOCKS;
        __shared__ float scx[NGT], scy[NGT], swd[NGT], shd[NGT];
        __shared__ int scell[NGT][3];
        __shared__ int s_a19;
        __shared__ float s_out[2][7];
        __shared__ int s_pos_t[NGT];   // global row index of each positive
        __shared__ int s_pos_lbl[NGT]; // label-1 of each positive
        __shared__ int s_npos;
        __shared__ float s_cls;

        if (tid == 0) { s_npos = 0; s_cls = 0.0f; }
        if (tid < NGT) {
            const float* p = gb + (b * NGT + tid) * 4;
            float l = p[0], tp = p[1], r = p[2], bo = p[3];
            float cx = (l + r) * 0.5f, cy = (tp + bo) * 0.5f;
            float w = r - l, h = bo - tp;
            scx[tid] = cx; scy[tid] = cy; swd[tid] = w; shd[tid] = h;
            #pragma unroll
            for (int j = 0; j < 3; j++) {
                int grid = grid_of(j), off = off_of(j);
                int col = (int)(cx * (float)grid);
                int row = (int)(cy * (float)grid);
                scell[tid][j] = (off + row * grid + col) * 3;
            }
            if (tid == NGT - 1) {
                // anchor argmax for GT #19 (only k whose positive events survive)
                float area = w * h;
                float best = -1.0f; int bi = 0;
                #pragma unroll
                for (int a = 0; a < 9; a++) {
                    float aw = c_anc[a][0], ah = c_anc[a][1];
                    float inter = fminf(w, aw) * fminf(h, ah);
                    float uni = area + aw * ah - inter;
                    float iou = inter / uni;
                    if (iou > best) { best = iou; bi = a; }  // first-max like argmax
                }
                s_a19 = bi;
            }
        }
        __syncthreads();

        float v1 = 0.f, v2 = 0.f, v3 = 0.f, v4 = 0.f, v5 = 0.f, v6 = 0.f;
        // v: txty, twth, npos, conf_pos, negsub, touched (cls handled in phase 3)

        if (tid < NGT * 3) {
            int i = tid / 3;
            int j = tid % 3;
            int C = scell[i][j];
            // owner = max-i sharing this (cell, scale)
            bool owner = true;
            for (int i2 = i + 1; i2 < NGT; i2++)
                if (scell[i2][j] == C) { owner = false; break; }

            if (owner) {
                int t0 = b * HWA + C;
                float sc0 = sigf(pconf[t0]);
                float sc1 = sigf(pconf[t0 + 1]);
                float sc2 = sigf(pconf[t0 + 2]);
                v5 = sc0 * sc0 + sc1 * sc1 + sc2 * sc2;
                v6 = 3.0f;

                int a19 = s_a19;
                int js = a19 / 3, ss = a19 % 3;
                if (j == js) {
                    int t = t0 + ss;
                    float sc = (ss == 0) ? sc0 : ((ss == 1) ? sc1 : sc2);
                    float d = sc - 1.0f;
                    v4 = d * d;
                    v3 = 1.0f;

                    float cx = scx[i], cy = scy[i], w = swd[i], h = shd[i];
                    float gridf = (float)grid_of(j);
                    int col = (int)(cx * gridf);
                    int rowg = (int)(cy * gridf);
                    float tx = (cx - (float)col / gridf) * gridf;
                    float ty = (cy - (float)rowg / gridf) * gridf;
                    float twx = __logf(w / c_anc[a19][0]);
                    float twy = __logf(h / c_anc[a19][1]);
                    float wt = 2.0f - w * h;

                    const float* pt = ptxywh + (size_t)t * 4;
                    float p0 = sigf(pt[0]);
                    float p1 = sigf(pt[1]);
                    v1 = (bcef(p0, tx) + bcef(p1, ty)) * wt;
                    float d2 = pt[2] - twx, d3 = pt[3] - twy;
                    v2 = (d2 * d2 + d3 * d3) * wt;

                    // enqueue positive row for parallel 80-class BCE
                    int slot = atomicAdd(&s_npos, 1);
                    s_pos_t[slot] = t;
                    s_pos_lbl[slot] = glab[b * NGT + i] - 1;
                }
            }
        }

        // reduce v1..v6 on warps 0,1 (only tid<60 carry data)
        if (warp < 2) {
            v1 = warp_sum_f(v1); v2 = warp_sum_f(v2); v3 = warp_sum_f(v3);
            v4 = warp_sum_f(v4); v5 = warp_sum_f(v5); v6 = warp_sum_f(v6);
            if (lane == 0) {
                s_out[warp][1] = v1; s_out[warp][2] = v2; s_out[warp][3] = v3;
                s_out[warp][4] = v4; s_out[warp][5] = v5; s_out[warp][6] = v6;
            }
        }
        __syncthreads();

        // ---- phase 3: 80-class BCE, one warp per positive row, 8-way parallel ----
        int npos = s_npos;
        for (int p = warp; p < npos; p += THREADS / 32) {
            int t = s_pos_t[p];
            int lbl = s_pos_lbl[p];
            const float* pcp = pcls + (size_t)t * NUM_CLASSES;
            float cls = 0.0f;
            #pragma unroll
            for (int c0 = 0; c0 < NUM_CLASSES; c0 += 32) {
                int c = c0 + lane;
                if (c < NUM_CLASSES) {
                    float p_ = sigf(pcp[c]);
                    p_ = fminf(fmaxf(p_, BCE_EPS), 1.0f - BCE_EPS);
                    cls += (c == lbl) ? -__logf(p_) : -__logf(1.0f - p_);
                }
            }
            cls = warp_sum_f(cls);
            if (lane == 0) atomicAdd(&s_cls, cls);
        }
        __syncthreads();

        if (tid == 0) g_batch[b][0] = s_cls;
        if (tid >= 1 && tid < 7) g_batch[b][tid] = s_out[0][tid] + s_out[1][tid];
    }

    // ---- last-block-done: final combine ----
    __shared__ unsigned int s_is_last;
    if (tid == 0) {
        __threadfence();
        unsigned int prev = atomicAdd(&g_done, 1u);
        s_is_last = (prev == (unsigned int)(GRID_BLOCKS - 1)) ? 1u : 0u;
    }
    __syncthreads();
    if (!s_is_last) return;
    if (tid == 0) __threadfence();
    __syncthreads();

    // sum main partials (333 floats)
    float part = 0.0f;
    for (int i = tid; i < MAIN_BLOCKS; i += THREADS) part += g_part_sum[i];
    part = warp_sum_f(part);
    if (lane == 0) sh_red[warp] = part;
    __syncthreads();
    __shared__ float sh_all;
    if (tid == 0) {
        float t = 0.0f;
        #pragma unroll
        for (int w = 0; w < THREADS / 32; w++) t += sh_red[w];
        sh_all = t;
    }

    float pb = 0.0f, npos = 0.0f, cpos = 0.0f, negsub = 0.0f, touched = 0.0f;
    if (tid < BATCH) {
        int b = tid;
        float np = g_batch[b][3];
        float npc = (np < FP16_EPS_F) ? FP16_EPS_F : np;
        pb = (g_batch[b][0] + g_batch[b][1] + g_batch[b][2]) / npc;
        npos = np;
        cpos = g_batch[b][4];
        negsub = g_batch[b][5];
        touched = g_batch[b][6];
    }
    if (tid < 32) {
        pb = warp_sum_f(pb);
        npos = warp_sum_f(npos);
        cpos = warp_sum_f(cpos);
        negsub = warp_sum_f(negsub);
        touched = warp_sum_f(touched);
    }
    __syncthreads();
    if (tid == 0) {
        double conf_neg_sum = (double)sh_all - (double)negsub;
        double neg_count = (double)TOTAL - (double)touched;
        double l_conf_pos = (double)cpos / (double)npos * 30.0;
        double l_conf_neg = conf_neg_sum / neg_count * 30.0;
        out[0] = (float)(l_conf_pos + l_conf_neg + (double)pb / (double)BATCH);
        g_done = 0u;  // self-reset for next graph replay
    }
}

extern "C" void kernel_launch(void* const* d_in, const int* in_sizes, int n_in,
                              void* d_out, int out_size) {
    const float* pconf  = (const float*)d_in[0];
    const float* pcls   = (const float*)d_in[1];
    const float* ptxywh = (const float*)d_in[2];
    const float* gb     = (const float*)d_in[3];
    const int*   glab   = (const int*)d_in[4];
    float* out = (float*)d_out;

    yolo_loss_kernel<<<GRID_BLOCKS, THREADS>>>(pconf, pcls, ptxywh, gb, glab, out);
}

// round 7
// speedup vs baseline: 5.0125x; 1.2500x over previous
#include <cuda_runtime.h>
#include <cuda_bf16.h>
#include <math.h>

#define BATCH 32
#define NGT 20
#define HWA 10647
#define NUM_CLASSES 80
#define FP16_EPS_F 0.0009765625
#define BCE_EPS 1e-6f

#define TOTAL (BATCH * HWA)     // 340704
#define TOTAL4 (TOTAL / 4)      // 85176 exact
#define THREADS 256
#define MAIN_BLOCKS 333         // 333*256 = 85248 >= TOTAL4, 1 float4/thread
#define GRID_BLOCKS (MAIN_BLOCKS + BATCH)  // 365

// persistent device state (plain-stored every call; no zeroing needed)
// g_batch[b]: [0]=cls [1]=txty [2]=twth [3]=npos [4]=conf_pos [5]=negsub [6]=touched
__device__ float g_part_sum[MAIN_BLOCKS];
__device__ float g_batch[BATCH][7];
__device__ unsigned int g_done;  // zero-init; self-reset by final block

__constant__ float c_anc[9][2] = {
    {0.024f, 0.031f}, {0.038f, 0.072f}, {0.079f, 0.055f},
    {0.072f, 0.147f}, {0.149f, 0.108f}, {0.142f, 0.286f},
    {0.279f, 0.216f}, {0.375f, 0.476f}, {0.897f, 0.784f}};

__device__ __forceinline__ int grid_of(int j) { return (j == 0) ? 52 : ((j == 1) ? 26 : 13); }
__device__ __forceinline__ int off_of(int j)  { return (j == 0) ? 0  : ((j == 1) ? 2704 : 3380); }

// fast sigmoid: EX2 + RCP. Used identically for main sum and touched-row
// subtraction so the correction cancels to ~1ulp.
__device__ __forceinline__ float sigf(float x) {
    return __fdividef(1.0f, 1.0f + __expf(-x));
}
__device__ __forceinline__ float bcef(float p, float g) {
    p = fminf(fmaxf(p, BCE_EPS), 1.0f - BCE_EPS);
    return -(g * __logf(p) + (1.0f - g) * __logf(1.0f - p));
}

__device__ __forceinline__ float warp_sum_f(float v) {
    #pragma unroll
    for (int s = 16; s > 0; s >>= 1) v += __shfl_xor_sync(0xFFFFFFFFu, v, s);
    return v;
}

__global__ void __launch_bounds__(THREADS)
yolo_loss_kernel(const float* __restrict__ pconf,
                 const float* __restrict__ pcls,
                 const float* __restrict__ ptxywh,
                 const float* __restrict__ gb,
                 const int* __restrict__ glab,
                 float* __restrict__ out) {
    __shared__ float sh_red[THREADS / 32];
    int blk = blockIdx.x;
    int tid = threadIdx.x;
    int lane = tid & 31, warp = tid >> 5;

    if (blk >= BATCH) {
        // ---- main: sum sigmoid(pconf)^2 over all rows, 1 float4/thread ----
        int mb = blk - BATCH;
        int idx = mb * THREADS + tid;
        float acc = 0.0f;
        if (idx < TOTAL4) {
            float4 v = ((const float4*)pconf)[idx];
            float s0 = sigf(v.x), s1 = sigf(v.y), s2 = sigf(v.z), s3 = sigf(v.w);
            acc = s0 * s0 + s1 * s1 + s2 * s2 + s3 * s3;
        }
        acc = warp_sum_f(acc);
        if (lane == 0) sh_red[warp] = acc;
        __syncthreads();
        if (tid == 0) {
            float t = 0.0f;
            #pragma unroll
            for (int w = 0; w < THREADS / 32; w++) t += sh_red[w];
            g_part_sum[mb] = t;
        }
    } else {
        // ---- correction: one block per batch item (closed-form winners) ----
        int b = blk;
        __shared__ float scx[NGT], scy[NGT], swd[NGT], shd[NGT];
        __shared__ int scell[NGT][3];
        __shared__ int sglab[NGT];
        __shared__ int s_a19;
        __shared__ float s_out[2][6];   // v1..v6 partials from warps 0,1
        __shared__ float s_cls;

        if (tid == 0) s_cls = 0.0f;
        if (tid < NGT) {
            const float* p = gb + (b * NGT + tid) * 4;
            float l = p[0], tp = p[1], r = p[2], bo = p[3];
            sglab[tid] = glab[b * NGT + tid];
            float cx = (l + r) * 0.5f, cy = (tp + bo) * 0.5f;
            float w = r - l, h = bo - tp;
            scx[tid] = cx; scy[tid] = cy; swd[tid] = w; shd[tid] = h;
            #pragma unroll
            for (int j = 0; j < 3; j++) {
                int grid = grid_of(j), off = off_of(j);
                int col = (int)(cx * (float)grid);
                int row = (int)(cy * (float)grid);
                scell[tid][j] = (off + row * grid + col) * 3;
            }
            if (tid == NGT - 1) {
                // anchor argmax for GT #19 (only k whose positive events survive)
                float area = w * h;
                float best = -1.0f; int bi = 0;
                #pragma unroll
                for (int a = 0; a < 9; a++) {
                    float aw = c_anc[a][0], ah = c_anc[a][1];
                    float inter = fminf(w, aw) * fminf(h, ah);
                    float uni = area + aw * ah - inter;
                    float iou = inter / uni;
                    if (iou > best) { best = iou; bi = a; }  // first-max like argmax
                }
                s_a19 = bi;
            }
        }
        __syncthreads();

        int a19 = s_a19;
        int js = a19 / 3, ss = a19 % 3;

        // ---- phase B: per-candidate conf/txty/twth (tid < 60) ----
        float v1 = 0.f, v2 = 0.f, v3 = 0.f, v4 = 0.f, v5 = 0.f, v6 = 0.f;
        // v: txty, twth, npos, conf_pos, negsub, touched
        if (tid < NGT * 3) {
            int i = tid / 3;
            int j = tid % 3;
            int C = scell[i][j];
            bool owner = true;   // owner = max-i sharing this (cell, scale)
            for (int i2 = i + 1; i2 < NGT; i2++)
                if (scell[i2][j] == C) { owner = false; break; }

            if (owner) {
                int t0 = b * HWA + C;
                float sc0 = sigf(pconf[t0]);
                float sc1 = sigf(pconf[t0 + 1]);
                float sc2 = sigf(pconf[t0 + 2]);
                v5 = sc0 * sc0 + sc1 * sc1 + sc2 * sc2;
                v6 = 3.0f;

                if (j == js) {
                    int t = t0 + ss;
                    float sc = (ss == 0) ? sc0 : ((ss == 1) ? sc1 : sc2);
                    float d = sc - 1.0f;
                    v4 = d * d;
                    v3 = 1.0f;

                    float cx = scx[i], cy = scy[i], w = swd[i], h = shd[i];
                    float gridf = (float)grid_of(j);
                    int col = (int)(cx * gridf);
                    int rowg = (int)(cy * gridf);
                    float tx = (cx - (float)col / gridf) * gridf;
                    float ty = (cy - (float)rowg / gridf) * gridf;
                    float twx = __logf(w / c_anc[a19][0]);
                    float twy = __logf(h / c_anc[a19][1]);
                    float wt = 2.0f - w * h;

                    const float* pt = ptxywh + (size_t)t * 4;
                    float p0 = sigf(pt[0]);
                    float p1 = sigf(pt[1]);
                    v1 = (bcef(p0, tx) + bcef(p1, ty)) * wt;
                    float d2 = pt[2] - twx, d3 = pt[3] - twy;
                    v2 = (d2 * d2 + d3 * d3) * wt;
                }
            }
        }

        // ---- phase C: 80-class BCE for positive rows, all 8 warps, smem-only
        //      gating (no dependence on phase B's loads -> overlapped gathers)
        for (int i = warp; i < NGT; i += THREADS / 32) {
            int C = scell[i][js];
            bool owner = true;
            for (int i2 = i + 1; i2 < NGT; i2++)
                if (scell[i2][js] == C) { owner = false; break; }
            if (!owner) continue;

            int t = b * HWA + C + ss;
            int lbl = sglab[i] - 1;
            const float* pcp = pcls + (size_t)t * NUM_CLASSES;
            float cls = 0.0f;
            #pragma unroll
            for (int c0 = 0; c0 < NUM_CLASSES; c0 += 32) {
                int c = c0 + lane;
                if (c < NUM_CLASSES) {
                    float p_ = sigf(pcp[c]);
                    p_ = fminf(fmaxf(p_, BCE_EPS), 1.0f - BCE_EPS);
                    cls += (c == lbl) ? -__logf(p_) : -__logf(1.0f - p_);
                }
            }
            cls = warp_sum_f(cls);
            if (lane == 0) atomicAdd(&s_cls, cls);
        }

        // reduce v1..v6 on warps 0,1 (only tid<60 carry data)
        if (warp < 2) {
            v1 = warp_sum_f(v1); v2 = warp_sum_f(v2); v3 = warp_sum_f(v3);
            v4 = warp_sum_f(v4); v5 = warp_sum_f(v5); v6 = warp_sum_f(v6);
            if (lane == 0) {
                s_out[warp][0] = v1; s_out[warp][1] = v2; s_out[warp][2] = v3;
                s_out[warp][3] = v4; s_out[warp][4] = v5; s_out[warp][5] = v6;
            }
        }
        __syncthreads();
        if (tid == 0) g_batch[b][0] = s_cls;
        if (tid >= 1 && tid < 7) g_batch[b][tid] = s_out[0][tid - 1] + s_out[1][tid - 1];
    }

    // ---- last-block-done: final combine ----
    __shared__ unsigned int s_is_last;
    if (tid == 0) {
        __threadfence();
        unsigned int prev = atomicAdd(&g_done, 1u);
        s_is_last = (prev == (unsigned int)(GRID_BLOCKS - 1)) ? 1u : 0u;
    }
    __syncthreads();
    if (!s_is_last) return;
    if (tid == 0) __threadfence();
    __syncthreads();

    // sum main partials (333 floats)
    float part = 0.0f;
    for (int i = tid; i < MAIN_BLOCKS; i += THREADS) part += g_part_sum[i];
    part = warp_sum_f(part);
    if (lane == 0) sh_red[warp] = part;
    __syncthreads();
    __shared__ float sh_all;
    if (tid == 0) {
        float t = 0.0f;
        #pragma unroll
        for (int w = 0; w < THREADS / 32; w++) t += sh_red[w];
        sh_all = t;
    }

    float pb = 0.0f, npos = 0.0f, cpos = 0.0f, negsub = 0.0f, touched = 0.0f;
    if (tid < BATCH) {
        int b = tid;
        float np = g_batch[b][3];
        float npc = (np < FP16_EPS_F) ? FP16_EPS_F : np;
        pb = (g_batch[b][0] + g_batch[b][1] + g_batch[b][2]) / npc;
        npos = np;
        cpos = g_batch[b][4];
        negsub = g_batch[b][5];
        touched = g_batch[b][6];
    }
    if (tid < 32) {
        pb = warp_sum_f(pb);
        npos = warp_sum_f(npos);
        cpos = warp_sum_f(cpos);
        negsub = warp_sum_f(negsub);
        touched = warp_sum_f(touched);
    }
    __syncthreads();
    if (tid == 0) {
        double conf_neg_sum = (double)sh_all - (double)negsub;
        double neg_count = (double)TOTAL - (double)touched;
        double l_conf_pos = (double)cpos / (double)npos * 30.0;
        double l_conf_neg = conf_neg_sum / neg_count * 30.0;
        out[0] = (float)(l_conf_pos + l_conf_neg + (double)pb / (double)BATCH);
        g_done = 0u;  // self-reset for next graph replay
    }
}

extern "C" void kernel_launch(void* const* d_in, const int* in_sizes, int n_in,
                              void* d_out, int out_size) {
    const float* pconf  = (const float*)d_in[0];
    const float* pcls   = (const float*)d_in[1];
    const float* ptxywh = (const float*)d_in[2];
    const float* gb     = (const float*)d_in[3];
    const int*   glab   = (const int*)d_in[4];
    float* out = (float*)d_out;

    yolo_loss_kernel<<<GRID_BLOCKS, THREADS>>>(pconf, pcls, ptxywh, gb, glab, out);
}